// round 5
// baseline (speedup 1.0000x reference)
#include <cuda_runtime.h>
#include <math.h>

// Problem constants
#define N_B    2
#define S_LEN  2048
#define T_LEN  2048
#define E_DIM  1024
#define H_NUM  16
#define HD     64
#define M_ROWS (N_B * S_LEN)   // 4096

// Scratch (device globals -> no runtime allocation)
__device__ float g_q [M_ROWS * E_DIM];   // holds tf32 bit patterns
__device__ float g_k [M_ROWS * E_DIM];   // holds tf32 bit patterns
__device__ float g_v [M_ROWS * E_DIM];   // holds tf32 bit patterns
__device__ float g_ao[M_ROWS * E_DIM];   // fp32

// ---------------------------------------------------------------------------
// tf32 helpers
// ---------------------------------------------------------------------------
__device__ __forceinline__ unsigned f2tf32(float f) {
    unsigned u;
    asm("cvt.rna.tf32.f32 %0, %1;" : "=r"(u) : "f"(f));
    return u;
}

// D = A(16x8, tf32, row) * B(8x8, tf32, col) + C  (fp32 accum, in-place)
__device__ __forceinline__ void mma_tf32(float* c, const unsigned* a, const unsigned* b) {
    asm volatile(
        "mma.sync.aligned.m16n8k8.row.col.f32.tf32.tf32.f32 "
        "{%0,%1,%2,%3}, {%4,%5,%6,%7}, {%8,%9}, {%0,%1,%2,%3};"
        : "+f"(c[0]), "+f"(c[1]), "+f"(c[2]), "+f"(c[3])
        : "r"(a[0]), "r"(a[1]), "r"(a[2]), "r"(a[3]), "r"(b[0]), "r"(b[1]));
}

// Column permutation: groups d by (d mod 8) so the 8 k-step fragment words
// of one thread are contiguous (enables LDS.128 fragment loads). d in [0,64).
__device__ __forceinline__ int cperm(int d) { return (d & 7) * 8 + (d >> 3); }

// ---------------------------------------------------------------------------
// GEMM (tf32 tensor core): C[M,1024] = (A[M,1024] @ W[1024,1024] + bias)*scale
// 128x128 CTA tile, BK=32, 256 threads = 8 warps (2x4), warp tile 64x32.
// tf32_out: store tf32 bit pattern instead of fp32 (for attention inputs).
// ---------------------------------------------------------------------------
#define ASTR 36
#define BSTR 136

__global__ __launch_bounds__(256, 2)
void gemm_tc(const float* __restrict__ A, const float* __restrict__ W,
             const float* __restrict__ bias, float* __restrict__ C,
             float scale, int tf32_out)
{
    __shared__ unsigned As[128 * ASTR];   // As[m][k]
    __shared__ unsigned Bs[32 * BSTR];    // Bs[k][n]

    const int tid  = threadIdx.x;
    const int lane = tid & 31;
    const int w    = tid >> 5;
    const int wm   = (w >> 2) * 64;
    const int wn   = (w & 3) * 32;
    const int m0   = blockIdx.y * 128;
    const int n0   = blockIdx.x * 128;

    float acc[4][4][4];
#pragma unroll
    for (int mi = 0; mi < 4; mi++)
#pragma unroll
        for (int ni = 0; ni < 4; ni++)
#pragma unroll
            for (int c = 0; c < 4; c++) acc[mi][ni][c] = 0.f;

    for (int kt = 0; kt < E_DIM; kt += 32) {
#pragma unroll
        for (int p = 0; p < 4; p++) {
            int f = tid + p * 256;
            int r = f >> 3;
            int c = (f & 7) << 2;
            float4 v = *(const float4*)(A + (size_t)(m0 + r) * E_DIM + kt + c);
            As[r * ASTR + c + 0] = f2tf32(v.x);
            As[r * ASTR + c + 1] = f2tf32(v.y);
            As[r * ASTR + c + 2] = f2tf32(v.z);
            As[r * ASTR + c + 3] = f2tf32(v.w);
        }
#pragma unroll
        for (int p = 0; p < 4; p++) {
            int f = tid + p * 256;
            int r = f >> 5;
            int c = (f & 31) << 2;
            float4 v = *(const float4*)(W + (size_t)(kt + r) * E_DIM + n0 + c);
            Bs[r * BSTR + c + 0] = f2tf32(v.x);
            Bs[r * BSTR + c + 1] = f2tf32(v.y);
            Bs[r * BSTR + c + 2] = f2tf32(v.z);
            Bs[r * BSTR + c + 3] = f2tf32(v.w);
        }
        __syncthreads();

#pragma unroll
        for (int kk = 0; kk < 4; kk++) {
            const int kb = kk * 8;
            unsigned af[4][4];
#pragma unroll
            for (int mi = 0; mi < 4; mi++) {
                int rbase = wm + mi * 16 + (lane >> 2);
                int cbase = kb + (lane & 3);
                af[mi][0] = As[rbase * ASTR + cbase];
                af[mi][1] = As[(rbase + 8) * ASTR + cbase];
                af[mi][2] = As[rbase * ASTR + cbase + 4];
                af[mi][3] = As[(rbase + 8) * ASTR + cbase + 4];
            }
            unsigned bf[4][2];
#pragma unroll
            for (int ni = 0; ni < 4; ni++) {
                int kbase = kb + (lane & 3);
                int nbase = wn + ni * 8 + (lane >> 2);
                bf[ni][0] = Bs[kbase * BSTR + nbase];
                bf[ni][1] = Bs[(kbase + 4) * BSTR + nbase];
            }
#pragma unroll
            for (int mi = 0; mi < 4; mi++)
#pragma unroll
                for (int ni = 0; ni < 4; ni++)
                    mma_tf32(acc[mi][ni], af[mi], bf[ni]);
        }
        __syncthreads();
    }

#pragma unroll
    for (int mi = 0; mi < 4; mi++) {
#pragma unroll
        for (int ni = 0; ni < 4; ni++) {
            int row = m0 + wm + mi * 16 + (lane >> 2);
            int col = n0 + wn + ni * 8 + 2 * (lane & 3);
            float v00 = (acc[mi][ni][0] + bias[col])     * scale;
            float v01 = (acc[mi][ni][1] + bias[col + 1]) * scale;
            float v10 = (acc[mi][ni][2] + bias[col])     * scale;
            float v11 = (acc[mi][ni][3] + bias[col + 1]) * scale;
            float2 o0, o1;
            if (tf32_out) {
                o0.x = __uint_as_float(f2tf32(v00));
                o0.y = __uint_as_float(f2tf32(v01));
                o1.x = __uint_as_float(f2tf32(v10));
                o1.y = __uint_as_float(f2tf32(v11));
            } else {
                o0.x = v00; o0.y = v01; o1.x = v10; o1.y = v11;
            }
            *(float2*)(C + (size_t)row * E_DIM + col)       = o0;
            *(float2*)(C + (size_t)(row + 8) * E_DIM + col) = o1;
        }
    }
}

// ---------------------------------------------------------------------------
// Flash attention v2, tf32 tensor core.
// CTA = 128 threads (4 warps), q-tile = 128 (warp w owns rows 32w..32w+31,
// two m16 tiles mi=0,1). T tiled by 64. Inputs are pre-converted tf32 bits;
// Q pre-scaled by 1/sqrt(HD).
// Smem (stride 68, permuted columns via cperm):
//   Qp[128][*] [q][perm d] | Kp[64][*] [t][perm d] | Vt[64][*] [d][perm t]
//   Pp[128][*] [q][perm t]
// ---------------------------------------------------------------------------
#define PSTR 68
#define SM_QP 0
#define SM_KP (128 * PSTR)
#define SM_VT (SM_KP + 64 * PSTR)
#define SM_PP (SM_VT + 64 * PSTR)
#define SM_TOTAL ((SM_PP + 128 * PSTR) * 4)   // 384*68*4 = 104448 B

__global__ __launch_bounds__(128, 2)
void flash_attn_tc2(const unsigned* __restrict__ Q, const unsigned* __restrict__ K,
                    const unsigned* __restrict__ V, float* __restrict__ O)
{
    extern __shared__ unsigned sm[];
    unsigned* Qp = sm + SM_QP;
    unsigned* Kp = sm + SM_KP;
    unsigned* Vt = sm + SM_VT;
    unsigned* Pp = sm + SM_PP;

    const int tid  = threadIdx.x;
    const int lane = tid & 31;
    const int w    = tid >> 5;
    const int qr   = lane >> 2;     // 0..7
    const int qc   = lane & 3;      // 0..3
    const int wbase = w * 32;

    const int qb = blockIdx.x;      // 0..15
    const int h  = blockIdx.y;
    const int n  = blockIdx.z;

    const unsigned* Qbase = Q + (size_t)(n * S_LEN + qb * 128) * E_DIM + h * HD;
    const unsigned* Kbase = K + (size_t)(n * T_LEN) * E_DIM + h * HD;
    const unsigned* Vbase = V + (size_t)(n * T_LEN) * E_DIM + h * HD;

    // Fill Qp (128x64, permuted cols). 2048 uint4 loads over 128 threads.
#pragma unroll
    for (int p = 0; p < 16; p++) {
        int f = tid + p * 128;          // 0..2047
        int r = f >> 4;                 // 0..127
        int d = (f & 15) << 2;          // 0..60
        uint4 v = *(const uint4*)(Qbase + (size_t)r * E_DIM + d);
        Qp[r * PSTR + cperm(d + 0)] = v.x;
        Qp[r * PSTR + cperm(d + 1)] = v.y;
        Qp[r * PSTR + cperm(d + 2)] = v.z;
        Qp[r * PSTR + cperm(d + 3)] = v.w;
    }

    float oacc[2][8][4];
#pragma unroll
    for (int mi = 0; mi < 2; mi++)
#pragma unroll
        for (int nt = 0; nt < 8; nt++)
#pragma unroll
            for (int c = 0; c < 4; c++) oacc[mi][nt][c] = 0.f;
    float mr[2][2], lr[2][2];
#pragma unroll
    for (int mi = 0; mi < 2; mi++)
#pragma unroll
        for (int hf = 0; hf < 2; hf++) { mr[mi][hf] = -1e30f; lr[mi][hf] = 0.f; }

    for (int t0 = 0; t0 < T_LEN; t0 += 64) {
        // Fill K tile [t][perm d] and V tile transposed [d][perm t]
#pragma unroll
        for (int p = 0; p < 8; p++) {
            int f = tid + p * 128;       // 0..1023
            int r = f >> 4;              // 0..63 (t within tile)
            int d = (f & 15) << 2;       // 0..60
            uint4 kv = *(const uint4*)(Kbase + (size_t)(t0 + r) * E_DIM + d);
            Kp[r * PSTR + cperm(d + 0)] = kv.x;
            Kp[r * PSTR + cperm(d + 1)] = kv.y;
            Kp[r * PSTR + cperm(d + 2)] = kv.z;
            Kp[r * PSTR + cperm(d + 3)] = kv.w;
            uint4 vv = *(const uint4*)(Vbase + (size_t)(t0 + r) * E_DIM + d);
            int tp = cperm(r);
            Vt[(d + 0) * PSTR + tp] = vv.x;
            Vt[(d + 1) * PSTR + tp] = vv.y;
            Vt[(d + 2) * PSTR + tp] = vv.z;
            Vt[(d + 3) * PSTR + tp] = vv.w;
        }
        __syncthreads();

        // ---- S = Q K^T ----
        float sacc[2][8][4];
#pragma unroll
        for (int mi = 0; mi < 2; mi++)
#pragma unroll
            for (int nt = 0; nt < 8; nt++)
#pragma unroll
                for (int c = 0; c < 4; c++) sacc[mi][nt][c] = 0.f;

#pragma unroll
        for (int mi = 0; mi < 2; mi++) {
            unsigned a[4][8];
            {
                int r0 = (wbase + mi * 16 + qr) * PSTR;
                int r1 = r0 + 8 * PSTR;
                *(uint4*)&a[0][0] = *(const uint4*)&Qp[r0 + qc * 8];
                *(uint4*)&a[0][4] = *(const uint4*)&Qp[r0 + qc * 8 + 4];
                *(uint4*)&a[1][0] = *(const uint4*)&Qp[r1 + qc * 8];
                *(uint4*)&a[1][4] = *(const uint4*)&Qp[r1 + qc * 8 + 4];
                *(uint4*)&a[2][0] = *(const uint4*)&Qp[r0 + (qc + 4) * 8];
                *(uint4*)&a[2][4] = *(const uint4*)&Qp[r0 + (qc + 4) * 8 + 4];
                *(uint4*)&a[3][0] = *(const uint4*)&Qp[r1 + (qc + 4) * 8];
                *(uint4*)&a[3][4] = *(const uint4*)&Qp[r1 + (qc + 4) * 8 + 4];
            }
#pragma unroll
            for (int nt = 0; nt < 8; nt++) {
                unsigned b[2][8];
                int br = (nt * 8 + qr) * PSTR;
                *(uint4*)&b[0][0] = *(const uint4*)&Kp[br + qc * 8];
                *(uint4*)&b[0][4] = *(const uint4*)&Kp[br + qc * 8 + 4];
                *(uint4*)&b[1][0] = *(const uint4*)&Kp[br + (qc + 4) * 8];
                *(uint4*)&b[1][4] = *(const uint4*)&Kp[br + (qc + 4) * 8 + 4];
#pragma unroll
                for (int kk = 0; kk < 8; kk++) {
                    unsigned af[4] = {a[0][kk], a[1][kk], a[2][kk], a[3][kk]};
                    unsigned bf[2] = {b[0][kk], b[1][kk]};
                    mma_tf32(sacc[mi][nt], af, bf);
                }
            }
        }

        // ---- online softmax ----
#pragma unroll
        for (int mi = 0; mi < 2; mi++) {
#pragma unroll
            for (int hf = 0; hf < 2; hf++) {
                float mx = -1e30f;
#pragma unroll
                for (int nt = 0; nt < 8; nt++)
                    mx = fmaxf(mx, fmaxf(sacc[mi][nt][2 * hf], sacc[mi][nt][2 * hf + 1]));
                mx = fmaxf(mx, __shfl_xor_sync(0xffffffffu, mx, 1));
                mx = fmaxf(mx, __shfl_xor_sync(0xffffffffu, mx, 2));
                float mn = fmaxf(mr[mi][hf], mx);
                float al = __expf(mr[mi][hf] - mn);
                mr[mi][hf] = mn;
                float ls = 0.f;
                int prow = (wbase + mi * 16 + qr + 8 * hf) * PSTR;
#pragma unroll
                for (int nt = 0; nt < 8; nt++) {
                    float p0 = __expf(sacc[mi][nt][2 * hf]     - mn);
                    float p1 = __expf(sacc[mi][nt][2 * hf + 1] - mn);
                    ls += p0 + p1;
                    Pp[prow + (2 * qc) * 8 + nt]     = f2tf32(p0);
                    Pp[prow + (2 * qc + 1) * 8 + nt] = f2tf32(p1);
                    oacc[mi][nt][2 * hf]     *= al;
                    oacc[mi][nt][2 * hf + 1] *= al;
                }
                ls += __shfl_xor_sync(0xffffffffu, ls, 1);
                ls += __shfl_xor_sync(0xffffffffu, ls, 2);
                lr[mi][hf] = lr[mi][hf] * al + ls;
            }
        }
        __syncwarp();   // Pp rows of this warp visible warp-wide

        // ---- O += P V ----
#pragma unroll
        for (int mi = 0; mi < 2; mi++) {
            unsigned a[4][8];
            {
                int r0 = (wbase + mi * 16 + qr) * PSTR;
                int r1 = r0 + 8 * PSTR;
                *(uint4*)&a[0][0] = *(const uint4*)&Pp[r0 + qc * 8];
                *(uint4*)&a[0][4] = *(const uint4*)&Pp[r0 + qc * 8 + 4];
                *(uint4*)&a[1][0] = *(const uint4*)&Pp[r1 + qc * 8];
                *(uint4*)&a[1][4] = *(const uint4*)&Pp[r1 + qc * 8 + 4];
                *(uint4*)&a[2][0] = *(const uint4*)&Pp[r0 + (qc + 4) * 8];
                *(uint4*)&a[2][4] = *(const uint4*)&Pp[r0 + (qc + 4) * 8 + 4];
                *(uint4*)&a[3][0] = *(const uint4*)&Pp[r1 + (qc + 4) * 8];
                *(uint4*)&a[3][4] = *(const uint4*)&Pp[r1 + (qc + 4) * 8 + 4];
            }
#pragma unroll
            for (int nt = 0; nt < 8; nt++) {
                unsigned b[2][8];
                int br = (nt * 8 + qr) * PSTR;   // Vt rows are d
                *(uint4*)&b[0][0] = *(const uint4*)&Vt[br + qc * 8];
                *(uint4*)&b[0][4] = *(const uint4*)&Vt[br + qc * 8 + 4];
                *(uint4*)&b[1][0] = *(const uint4*)&Vt[br + (qc + 4) * 8];
                *(uint4*)&b[1][4] = *(const uint4*)&Vt[br + (qc + 4) * 8 + 4];
#pragma unroll
                for (int kk = 0; kk < 8; kk++) {
                    unsigned af[4] = {a[0][kk], a[1][kk], a[2][kk], a[3][kk]};
                    unsigned bf[2] = {b[0][kk], b[1][kk]};
                    mma_tf32(oacc[mi][nt], af, bf);
                }
            }
        }
        __syncthreads();   // Kp/Vt consumed; safe to refill next iter
    }

    // Normalize and write out
#pragma unroll
    for (int mi = 0; mi < 2; mi++) {
        float inv0 = 1.f / lr[mi][0];
        float inv1 = 1.f / lr[mi][1];
        int row0 = n * S_LEN + qb * 128 + wbase + mi * 16 + qr;
        int gcol = h * HD + 2 * qc;
#pragma unroll
        for (int nt = 0; nt < 8; nt++) {
            float2 o0, o1;
            o0.x = oacc[mi][nt][0] * inv0;
            o0.y = oacc[mi][nt][1] * inv0;
            o1.x = oacc[mi][nt][2] * inv1;
            o1.y = oacc[mi][nt][3] * inv1;
            *(float2*)(O + (size_t)row0 * E_DIM + gcol + nt * 8)       = o0;
            *(float2*)(O + (size_t)(row0 + 8) * E_DIM + gcol + nt * 8) = o1;
        }
    }
}

// ---------------------------------------------------------------------------
// Launch
// ---------------------------------------------------------------------------
extern "C" void kernel_launch(void* const* d_in, const int* in_sizes, int n_in,
                              void* d_out, int out_size)
{
    const float* query = (const float*)d_in[0];
    const float* key   = (const float*)d_in[1];
    const float* value = (const float*)d_in[2];
    const float* Wq    = (const float*)d_in[3];
    const float* bq    = (const float*)d_in[4];
    const float* Wk    = (const float*)d_in[5];
    const float* bk    = (const float*)d_in[6];
    const float* Wv    = (const float*)d_in[7];
    const float* bv    = (const float*)d_in[8];
    const float* Wo    = (const float*)d_in[9];
    const float* bo    = (const float*)d_in[10];
    float* out = (float*)d_out;

    float *q_p, *k_p, *v_p, *ao_p;
    cudaGetSymbolAddress((void**)&q_p,  g_q);
    cudaGetSymbolAddress((void**)&k_p,  g_k);
    cudaGetSymbolAddress((void**)&v_p,  g_v);
    cudaGetSymbolAddress((void**)&ao_p, g_ao);

    dim3 gemm_grid(E_DIM / 128, M_ROWS / 128);   // 8 x 32

    // Projections write tf32 bit patterns; Q pre-scaled by 1/sqrt(HD) = 0.125
    gemm_tc<<<gemm_grid, 256>>>(query, Wq, bq, q_p, 0.125f, 1);
    gemm_tc<<<gemm_grid, 256>>>(key,   Wk, bk, k_p, 1.0f,   1);
    gemm_tc<<<gemm_grid, 256>>>(value, Wv, bv, v_p, 1.0f,   1);

    cudaFuncSetAttribute(flash_attn_tc2,
                         cudaFuncAttributeMaxDynamicSharedMemorySize, SM_TOTAL);
    dim3 attn_grid(S_LEN / 128, H_NUM, N_B);     // 16 x 16 x 2
    flash_attn_tc2<<<attn_grid, 128, SM_TOTAL>>>(
        (const unsigned*)q_p, (const unsigned*)k_p, (const unsigned*)v_p, ao_p);

    gemm_tc<<<gemm_grid, 256>>>(ao_p, Wo, bo, out, 1.0f, 0);
}

// round 6
// speedup vs baseline: 1.2456x; 1.2456x over previous
#include <cuda_runtime.h>
#include <math.h>

// Problem constants
#define N_B    2
#define S_LEN  2048
#define T_LEN  2048
#define E_DIM  1024
#define H_NUM  16
#define HD     64
#define M_ROWS (N_B * S_LEN)   // 4096

// Scratch (device globals -> no runtime allocation)
__device__ float g_q [M_ROWS * E_DIM];   // tf32 bit patterns
__device__ float g_k [M_ROWS * E_DIM];   // tf32 bit patterns
__device__ float g_v [M_ROWS * E_DIM];   // tf32 bit patterns
__device__ float g_ao[M_ROWS * E_DIM];   // fp32

// ---------------------------------------------------------------------------
// tf32 helpers
// ---------------------------------------------------------------------------
__device__ __forceinline__ unsigned f2tf32(float f) {
    unsigned u;
    asm("cvt.rna.tf32.f32 %0, %1;" : "=r"(u) : "f"(f));
    return u;
}

// D = A(16x8, tf32, row) * B(8x8, tf32, col) + C  (fp32 accum, in-place)
__device__ __forceinline__ void mma_tf32(float* c, const unsigned* a, const unsigned* b) {
    asm volatile(
        "mma.sync.aligned.m16n8k8.row.col.f32.tf32.tf32.f32 "
        "{%0,%1,%2,%3}, {%4,%5,%6,%7}, {%8,%9}, {%0,%1,%2,%3};"
        : "+f"(c[0]), "+f"(c[1]), "+f"(c[2]), "+f"(c[3])
        : "r"(a[0]), "r"(a[1]), "r"(a[2]), "r"(a[3]), "r"(b[0]), "r"(b[1]));
}

// ---------------------------------------------------------------------------
// GEMM (tf32 tensor core): C[M,1024] = (A[M,1024] @ W[1024,1024] + bias)*scale
// 128x128 CTA tile, BK=32, 256 threads = 8 warps (2x4), warp tile 64x32.
// tf32_out: store tf32 bit pattern instead of fp32 (for attention inputs).
// ---------------------------------------------------------------------------
#define ASTR 36
#define BSTR 136

__global__ __launch_bounds__(256, 2)
void gemm_tc(const float* __restrict__ A, const float* __restrict__ W,
             const float* __restrict__ bias, float* __restrict__ C,
             float scale, int tf32_out)
{
    __shared__ unsigned As[128 * ASTR];   // As[m][k]
    __shared__ unsigned Bs[32 * BSTR];    // Bs[k][n]

    const int tid  = threadIdx.x;
    const int lane = tid & 31;
    const int w    = tid >> 5;
    const int wm   = (w >> 2) * 64;
    const int wn   = (w & 3) * 32;
    const int m0   = blockIdx.y * 128;
    const int n0   = blockIdx.x * 128;

    float acc[4][4][4];
#pragma unroll
    for (int mi = 0; mi < 4; mi++)
#pragma unroll
        for (int ni = 0; ni < 4; ni++)
#pragma unroll
            for (int c = 0; c < 4; c++) acc[mi][ni][c] = 0.f;

    for (int kt = 0; kt < E_DIM; kt += 32) {
#pragma unroll
        for (int p = 0; p < 4; p++) {
            int f = tid + p * 256;
            int r = f >> 3;
            int c = (f & 7) << 2;
            float4 v = *(const float4*)(A + (size_t)(m0 + r) * E_DIM + kt + c);
            As[r * ASTR + c + 0] = f2tf32(v.x);
            As[r * ASTR + c + 1] = f2tf32(v.y);
            As[r * ASTR + c + 2] = f2tf32(v.z);
            As[r * ASTR + c + 3] = f2tf32(v.w);
        }
#pragma unroll
        for (int p = 0; p < 4; p++) {
            int f = tid + p * 256;
            int r = f >> 5;
            int c = (f & 31) << 2;
            float4 v = *(const float4*)(W + (size_t)(kt + r) * E_DIM + n0 + c);
            Bs[r * BSTR + c + 0] = f2tf32(v.x);
            Bs[r * BSTR + c + 1] = f2tf32(v.y);
            Bs[r * BSTR + c + 2] = f2tf32(v.z);
            Bs[r * BSTR + c + 3] = f2tf32(v.w);
        }
        __syncthreads();

#pragma unroll
        for (int kk = 0; kk < 4; kk++) {
            const int kb = kk * 8;
            unsigned af[4][4];
#pragma unroll
            for (int mi = 0; mi < 4; mi++) {
                int rbase = wm + mi * 16 + (lane >> 2);
                int cbase = kb + (lane & 3);
                af[mi][0] = As[rbase * ASTR + cbase];
                af[mi][1] = As[(rbase + 8) * ASTR + cbase];
                af[mi][2] = As[rbase * ASTR + cbase + 4];
                af[mi][3] = As[(rbase + 8) * ASTR + cbase + 4];
            }
            unsigned bf[4][2];
#pragma unroll
            for (int ni = 0; ni < 4; ni++) {
                int kbase = kb + (lane & 3);
                int nbase = wn + ni * 8 + (lane >> 2);
                bf[ni][0] = Bs[kbase * BSTR + nbase];
                bf[ni][1] = Bs[(kbase + 4) * BSTR + nbase];
            }
#pragma unroll
            for (int mi = 0; mi < 4; mi++)
#pragma unroll
                for (int ni = 0; ni < 4; ni++)
                    mma_tf32(acc[mi][ni], af[mi], bf[ni]);
        }
        __syncthreads();
    }

#pragma unroll
    for (int mi = 0; mi < 4; mi++) {
#pragma unroll
        for (int ni = 0; ni < 4; ni++) {
            int row = m0 + wm + mi * 16 + (lane >> 2);
            int col = n0 + wn + ni * 8 + 2 * (lane & 3);
            float v00 = (acc[mi][ni][0] + bias[col])     * scale;
            float v01 = (acc[mi][ni][1] + bias[col + 1]) * scale;
            float v10 = (acc[mi][ni][2] + bias[col])     * scale;
            float v11 = (acc[mi][ni][3] + bias[col + 1]) * scale;
            float2 o0, o1;
            if (tf32_out) {
                o0.x = __uint_as_float(f2tf32(v00));
                o0.y = __uint_as_float(f2tf32(v01));
                o1.x = __uint_as_float(f2tf32(v10));
                o1.y = __uint_as_float(f2tf32(v11));
            } else {
                o0.x = v00; o0.y = v01; o1.x = v10; o1.y = v11;
            }
            *(float2*)(C + (size_t)row * E_DIM + col)       = o0;
            *(float2*)(C + (size_t)(row + 8) * E_DIM + col) = o1;
        }
    }
}

// ---------------------------------------------------------------------------
// Flash attention, tf32 tensor core (R2 structure, pre-converted tf32 inputs).
// CTA = 128 threads (4 warps) per (n, h, 64-query block). T tiled by 64.
// Warp w owns score/O rows 16w..16w+15.
// Smem:
//   Qs[64][68] [q][d]  Ks[64][68] [t][d]  Ps[64][68] [q][t]  Vs[64][72] [t][d]
// ---------------------------------------------------------------------------
#define QSTR 68
#define VSTR 72
#define SM_Q  0
#define SM_K  (64 * QSTR)
#define SM_P  (2 * 64 * QSTR)
#define SM_V  (3 * 64 * QSTR)
#define SM_TOT (3 * 64 * QSTR + 64 * VSTR)   // 17664 uints = 70656 B

__global__ __launch_bounds__(128, 2)
void flash_attn_tc(const unsigned* __restrict__ Q, const unsigned* __restrict__ K,
                   const unsigned* __restrict__ V, float* __restrict__ O)
{
    extern __shared__ unsigned sm[];
    unsigned* Qs = sm + SM_Q;
    unsigned* Ks = sm + SM_K;
    unsigned* Ps = sm + SM_P;
    unsigned* Vs = sm + SM_V;

    const int tid  = threadIdx.x;
    const int lane = tid & 31;
    const int w    = tid >> 5;
    const int qb   = blockIdx.x;
    const int h    = blockIdx.y;
    const int n    = blockIdx.z;

    const int qr   = (lane >> 2);    // 0..7
    const int qc   = (lane & 3);     // 0..3

    const unsigned* Qbase = Q + (size_t)(n * S_LEN + qb * 64) * E_DIM + h * HD;
    const unsigned* Kbase = K + (size_t)(n * T_LEN) * E_DIM + h * HD;
    const unsigned* Vbase = V + (size_t)(n * T_LEN) * E_DIM + h * HD;

    // Load Q tile (64x64) — already tf32 bits, pure copy
#pragma unroll
    for (int p = 0; p < 8; p++) {
        int f = tid + p * 128;        // 0..1023
        int r = f >> 4;               // 0..63
        int c = (f & 15) << 2;        // 0..60
        uint4 v = *(const uint4*)(Qbase + (size_t)r * E_DIM + c);
        Qs[r * QSTR + c + 0] = v.x;
        Qs[r * QSTR + c + 1] = v.y;
        Qs[r * QSTR + c + 2] = v.z;
        Qs[r * QSTR + c + 3] = v.w;
    }

    float oacc[8][4];
#pragma unroll
    for (int nt = 0; nt < 8; nt++)
#pragma unroll
        for (int c = 0; c < 4; c++) oacc[nt][c] = 0.f;
    float mr0 = -1e30f, mr1 = -1e30f, lr0 = 0.f, lr1 = 0.f;

    for (int t0 = 0; t0 < T_LEN; t0 += 64) {
        // Load K and V tiles — pure copies
#pragma unroll
        for (int p = 0; p < 8; p++) {
            int f = tid + p * 128;
            int r = f >> 4;
            int c = (f & 15) << 2;
            uint4 kv = *(const uint4*)(Kbase + (size_t)(t0 + r) * E_DIM + c);
            Ks[r * QSTR + c + 0] = kv.x;
            Ks[r * QSTR + c + 1] = kv.y;
            Ks[r * QSTR + c + 2] = kv.z;
            Ks[r * QSTR + c + 3] = kv.w;
            uint4 vv = *(const uint4*)(Vbase + (size_t)(t0 + r) * E_DIM + c);
            *(uint4*)(Vs + r * VSTR + c) = vv;
        }
        __syncthreads();

        // S = Q * K^T   (Q pre-scaled by 1/sqrt(HD) in the projection)
        float sacc[8][4];
#pragma unroll
        for (int nt = 0; nt < 8; nt++)
#pragma unroll
            for (int c = 0; c < 4; c++) sacc[nt][c] = 0.f;

#pragma unroll
        for (int kk = 0; kk < 8; kk++) {
            const int kb = kk * 8;
            unsigned a[4];
            int rbase = (w * 16 + qr) * QSTR + kb + qc;
            a[0] = Qs[rbase];
            a[1] = Qs[rbase + 8 * QSTR];
            a[2] = Qs[rbase + 4];
            a[3] = Qs[rbase + 8 * QSTR + 4];
#pragma unroll
            for (int nt = 0; nt < 8; nt++) {
                unsigned b[2];
                int bi = (nt * 8 + qr) * QSTR + kb + qc;
                b[0] = Ks[bi];
                b[1] = Ks[bi + 4];
                mma_tf32(sacc[nt], a, b);
            }
        }

        // Online softmax: thread owns rows r0 = w*16+qr (c0,c1) and r0+8 (c2,c3)
        float mx0 = -1e30f, mx1 = -1e30f;
#pragma unroll
        for (int nt = 0; nt < 8; nt++) {
            mx0 = fmaxf(mx0, fmaxf(sacc[nt][0], sacc[nt][1]));
            mx1 = fmaxf(mx1, fmaxf(sacc[nt][2], sacc[nt][3]));
        }
        mx0 = fmaxf(mx0, __shfl_xor_sync(0xffffffffu, mx0, 1));
        mx0 = fmaxf(mx0, __shfl_xor_sync(0xffffffffu, mx0, 2));
        mx1 = fmaxf(mx1, __shfl_xor_sync(0xffffffffu, mx1, 1));
        mx1 = fmaxf(mx1, __shfl_xor_sync(0xffffffffu, mx1, 2));

        float mn0 = fmaxf(mr0, mx0);
        float mn1 = fmaxf(mr1, mx1);
        float al0 = __expf(mr0 - mn0);
        float al1 = __expf(mr1 - mn1);
        mr0 = mn0;
        mr1 = mn1;

        float ls0 = 0.f, ls1 = 0.f;
        int prow0 = (w * 16 + qr) * QSTR + 2 * qc;
        int prow1 = prow0 + 8 * QSTR;
#pragma unroll
        for (int nt = 0; nt < 8; nt++) {
            float p00 = __expf(sacc[nt][0] - mn0);
            float p01 = __expf(sacc[nt][1] - mn0);
            float p10 = __expf(sacc[nt][2] - mn1);
            float p11 = __expf(sacc[nt][3] - mn1);
            ls0 += p00 + p01;
            ls1 += p10 + p11;
            Ps[prow0 + nt * 8]     = f2tf32(p00);
            Ps[prow0 + nt * 8 + 1] = f2tf32(p01);
            Ps[prow1 + nt * 8]     = f2tf32(p10);
            Ps[prow1 + nt * 8 + 1] = f2tf32(p11);
            oacc[nt][0] *= al0;
            oacc[nt][1] *= al0;
            oacc[nt][2] *= al1;
            oacc[nt][3] *= al1;
        }
        ls0 += __shfl_xor_sync(0xffffffffu, ls0, 1);
        ls0 += __shfl_xor_sync(0xffffffffu, ls0, 2);
        ls1 += __shfl_xor_sync(0xffffffffu, ls1, 1);
        ls1 += __shfl_xor_sync(0xffffffffu, ls1, 2);
        lr0 = lr0 * al0 + ls0;
        lr1 = lr1 * al1 + ls1;

        __syncwarp();   // P rows of this warp visible warp-wide

        // O += P * V   (m=q16, k=t, n=d)
#pragma unroll
        for (int kk = 0; kk < 8; kk++) {
            const int kb = kk * 8;
            unsigned a[4];
            int rbase = (w * 16 + qr) * QSTR + kb + qc;
            a[0] = Ps[rbase];
            a[1] = Ps[rbase + 8 * QSTR];
            a[2] = Ps[rbase + 4];
            a[3] = Ps[rbase + 8 * QSTR + 4];
#pragma unroll
            for (int nt = 0; nt < 8; nt++) {
                unsigned b[2];
                int bi = (kb + qc) * VSTR + nt * 8 + qr;
                b[0] = Vs[bi];
                b[1] = Vs[bi + 4 * VSTR];
                mma_tf32(oacc[nt], a, b);
            }
        }
        __syncthreads();   // Ks/Vs consumed; safe to overwrite next iter
    }

    // Normalize and write out: O[n*S + qb*64 + row][h*64 + col]
    float inv0 = 1.f / lr0;
    float inv1 = 1.f / lr1;
    int grow0 = n * S_LEN + qb * 64 + w * 16 + qr;
    int gcol  = h * HD + 2 * qc;
#pragma unroll
    for (int nt = 0; nt < 8; nt++) {
        float2 o0, o1;
        o0.x = oacc[nt][0] * inv0;
        o0.y = oacc[nt][1] * inv0;
        o1.x = oacc[nt][2] * inv1;
        o1.y = oacc[nt][3] * inv1;
        *(float2*)(O + (size_t)grow0 * E_DIM + gcol + nt * 8)       = o0;
        *(float2*)(O + (size_t)(grow0 + 8) * E_DIM + gcol + nt * 8) = o1;
    }
}

// ---------------------------------------------------------------------------
// Launch
// ---------------------------------------------------------------------------
extern "C" void kernel_launch(void* const* d_in, const int* in_sizes, int n_in,
                              void* d_out, int out_size)
{
    const float* query = (const float*)d_in[0];
    const float* key   = (const float*)d_in[1];
    const float* value = (const float*)d_in[2];
    const float* Wq    = (const float*)d_in[3];
    const float* bq    = (const float*)d_in[4];
    const float* Wk    = (const float*)d_in[5];
    const float* bk    = (const float*)d_in[6];
    const float* Wv    = (const float*)d_in[7];
    const float* bv    = (const float*)d_in[8];
    const float* Wo    = (const float*)d_in[9];
    const float* bo    = (const float*)d_in[10];
    float* out = (float*)d_out;

    float *q_p, *k_p, *v_p, *ao_p;
    cudaGetSymbolAddress((void**)&q_p,  g_q);
    cudaGetSymbolAddress((void**)&k_p,  g_k);
    cudaGetSymbolAddress((void**)&v_p,  g_v);
    cudaGetSymbolAddress((void**)&ao_p, g_ao);

    dim3 gemm_grid(E_DIM / 128, M_ROWS / 128);   // 8 x 32

    // Projections write tf32 bit patterns; Q pre-scaled by 1/sqrt(HD) = 0.125
    gemm_tc<<<gemm_grid, 256>>>(query, Wq, bq, q_p, 0.125f, 1);
    gemm_tc<<<gemm_grid, 256>>>(key,   Wk, bk, k_p, 1.0f,   1);
    gemm_tc<<<gemm_grid, 256>>>(value, Wv, bv, v_p, 1.0f,   1);

    int smem_bytes = SM_TOT * (int)sizeof(unsigned);   // 70656
    cudaFuncSetAttribute(flash_attn_tc,
                         cudaFuncAttributeMaxDynamicSharedMemorySize, smem_bytes);
    dim3 attn_grid(S_LEN / 64, H_NUM, N_B);            // 32 x 16 x 2
    flash_attn_tc<<<attn_grid, 128, smem_bytes>>>(
        (const unsigned*)q_p, (const unsigned*)k_p, (const unsigned*)v_p, ao_p);

    gemm_tc<<<gemm_grid, 256>>>(ao_p, Wo, bo, out, 1.0f, 0);
}

// round 8
// speedup vs baseline: 1.2721x; 1.0212x over previous
#include <cuda_runtime.h>
#include <math.h>

// Problem constants
#define N_B    2
#define S_LEN  2048
#define T_LEN  2048
#define E_DIM  1024
#define H_NUM  16
#define HD     64
#define M_ROWS (N_B * S_LEN)   // 4096

// Scratch (device globals -> no runtime allocation)
__device__ float g_q [M_ROWS * E_DIM];   // tf32 bit patterns
__device__ float g_k [M_ROWS * E_DIM];   // tf32 bit patterns
__device__ float g_v [M_ROWS * E_DIM];   // tf32 bit patterns
__device__ float g_ao[M_ROWS * E_DIM];   // fp32

// ---------------------------------------------------------------------------
// tf32 helpers
// ---------------------------------------------------------------------------
__device__ __forceinline__ unsigned f2tf32(float f) {
    unsigned u;
    asm("cvt.rna.tf32.f32 %0, %1;" : "=r"(u) : "f"(f));
    return u;
}

// D = A(16x8, tf32, row) * B(8x8, tf32, col) + C  (fp32 accum, in-place)
__device__ __forceinline__ void mma_tf32(float* c, const unsigned* a, const unsigned* b) {
    asm volatile(
        "mma.sync.aligned.m16n8k8.row.col.f32.tf32.tf32.f32 "
        "{%0,%1,%2,%3}, {%4,%5,%6,%7}, {%8,%9}, {%0,%1,%2,%3};"
        : "+f"(c[0]), "+f"(c[1]), "+f"(c[2]), "+f"(c[3])
        : "r"(a[0]), "r"(a[1]), "r"(a[2]), "r"(a[3]), "r"(b[0]), "r"(b[1]));
}

// ---------------------------------------------------------------------------
// GEMM core (tf32 tensor core): C = (A @ W + bias) * scale
// 128x128 CTA tile, BK=32, 256 threads = 8 warps (2x4), warp tile 64x32.
// ---------------------------------------------------------------------------
#define ASTR 36
#define BSTR 136

__device__ __forceinline__
void gemm_body(const float* __restrict__ A, const float* __restrict__ W,
               const float* __restrict__ bias, float* __restrict__ C,
               float scale, int tf32_out, int m0, int n0,
               unsigned* As, unsigned* Bs)
{
    const int tid  = threadIdx.x;
    const int lane = tid & 31;
    const int w    = tid >> 5;
    const int wm   = (w >> 2) * 64;
    const int wn   = (w & 3) * 32;

    float acc[4][4][4];
#pragma unroll
    for (int mi = 0; mi < 4; mi++)
#pragma unroll
        for (int ni = 0; ni < 4; ni++)
#pragma unroll
            for (int c = 0; c < 4; c++) acc[mi][ni][c] = 0.f;

    for (int kt = 0; kt < E_DIM; kt += 32) {
#pragma unroll
        for (int p = 0; p < 4; p++) {
            int f = tid + p * 256;
            int r = f >> 3;
            int c = (f & 7) << 2;
            float4 v = *(const float4*)(A + (size_t)(m0 + r) * E_DIM + kt + c);
            As[r * ASTR + c + 0] = f2tf32(v.x);
            As[r * ASTR + c + 1] = f2tf32(v.y);
            As[r * ASTR + c + 2] = f2tf32(v.z);
            As[r * ASTR + c + 3] = f2tf32(v.w);
        }
#pragma unroll
        for (int p = 0; p < 4; p++) {
            int f = tid + p * 256;
            int r = f >> 5;
            int c = (f & 31) << 2;
            float4 v = *(const float4*)(W + (size_t)(kt + r) * E_DIM + n0 + c);
            Bs[r * BSTR + c + 0] = f2tf32(v.x);
            Bs[r * BSTR + c + 1] = f2tf32(v.y);
            Bs[r * BSTR + c + 2] = f2tf32(v.z);
            Bs[r * BSTR + c + 3] = f2tf32(v.w);
        }
        __syncthreads();

#pragma unroll
        for (int kk = 0; kk < 4; kk++) {
            const int kb = kk * 8;
            unsigned af[4][4];
#pragma unroll
            for (int mi = 0; mi < 4; mi++) {
                int rbase = wm + mi * 16 + (lane >> 2);
                int cbase = kb + (lane & 3);
                af[mi][0] = As[rbase * ASTR + cbase];
                af[mi][1] = As[(rbase + 8) * ASTR + cbase];
                af[mi][2] = As[rbase * ASTR + cbase + 4];
                af[mi][3] = As[(rbase + 8) * ASTR + cbase + 4];
            }
            unsigned bf[4][2];
#pragma unroll
            for (int ni = 0; ni < 4; ni++) {
                int kbase = kb + (lane & 3);
                int nbase = wn + ni * 8 + (lane >> 2);
                bf[ni][0] = Bs[kbase * BSTR + nbase];
                bf[ni][1] = Bs[(kbase + 4) * BSTR + nbase];
            }
#pragma unroll
            for (int mi = 0; mi < 4; mi++)
#pragma unroll
                for (int ni = 0; ni < 4; ni++)
                    mma_tf32(acc[mi][ni], af[mi], bf[ni]);
        }
        __syncthreads();
    }

#pragma unroll
    for (int mi = 0; mi < 4; mi++) {
#pragma unroll
        for (int ni = 0; ni < 4; ni++) {
            int row = m0 + wm + mi * 16 + (lane >> 2);
            int col = n0 + wn + ni * 8 + 2 * (lane & 3);
            float v00 = (acc[mi][ni][0] + bias[col])     * scale;
            float v01 = (acc[mi][ni][1] + bias[col + 1]) * scale;
            float v10 = (acc[mi][ni][2] + bias[col])     * scale;
            float v11 = (acc[mi][ni][3] + bias[col + 1]) * scale;
            float2 o0, o1;
            if (tf32_out) {
                o0.x = __uint_as_float(f2tf32(v00));
                o0.y = __uint_as_float(f2tf32(v01));
                o1.x = __uint_as_float(f2tf32(v10));
                o1.y = __uint_as_float(f2tf32(v11));
            } else {
                o0.x = v00; o0.y = v01; o1.x = v10; o1.y = v11;
            }
            *(float2*)(C + (size_t)row * E_DIM + col)       = o0;
            *(float2*)(C + (size_t)(row + 8) * E_DIM + col) = o1;
        }
    }
}

// Fused QKV projections: blockIdx.z selects (input, weight, bias, output, scale).
__global__ __launch_bounds__(256, 2)
void gemm_qkv(const float* __restrict__ query, const float* __restrict__ key,
              const float* __restrict__ value,
              const float* __restrict__ Wq, const float* __restrict__ bq,
              const float* __restrict__ Wk, const float* __restrict__ bk,
              const float* __restrict__ Wv, const float* __restrict__ bv,
              float* __restrict__ q_out, float* __restrict__ k_out,
              float* __restrict__ v_out)
{
    __shared__ unsigned As[128 * ASTR];
    __shared__ unsigned Bs[32 * BSTR];
    const int z = blockIdx.z;
    const float* A = (z == 0) ? query : (z == 1) ? key : value;
    const float* W = (z == 0) ? Wq    : (z == 1) ? Wk  : Wv;
    const float* b = (z == 0) ? bq    : (z == 1) ? bk  : bv;
    float*       C = (z == 0) ? q_out : (z == 1) ? k_out : v_out;
    float scale    = (z == 0) ? 0.125f : 1.0f;   // Q pre-scaled by 1/sqrt(HD)
    gemm_body(A, W, b, C, scale, 1, blockIdx.y * 128, blockIdx.x * 128, As, Bs);
}

// Output projection (fp32 out).
__global__ __launch_bounds__(256, 2)
void gemm_tc(const float* __restrict__ A, const float* __restrict__ W,
             const float* __restrict__ bias, float* __restrict__ C,
             float scale, int tf32_out)
{
    __shared__ unsigned As[128 * ASTR];
    __shared__ unsigned Bs[32 * BSTR];
    gemm_body(A, W, bias, C, scale, tf32_out,
              blockIdx.y * 128, blockIdx.x * 128, As, Bs);
}

// ---------------------------------------------------------------------------
// Flash attention, tf32 tensor core (pre-converted tf32 inputs).
// CTA = 128 threads (4 warps) per (n, h, 64-query block). T tiled by 64.
// Warp w owns score/O rows 16w..16w+15.
// Smem:
//   Qs[64][68] [q][d]  Ks[64][68] [t][d]  Ps[64][68] [q][t]  Vs[64][72] [t][d]
// Target 3 CTAs/SM (3 x 70656 B = 212 KB smem, regs <= 170).
// ---------------------------------------------------------------------------
#define QSTR 68
#define VSTR 72
#define SM_Q  0
#define SM_K  (64 * QSTR)
#define SM_P  (2 * 64 * QSTR)
#define SM_V  (3 * 64 * QSTR)
#define SM_TOT (3 * 64 * QSTR + 64 * VSTR)   // 17664 uints = 70656 B

__global__ __launch_bounds__(128, 3)
void flash_attn_tc(const unsigned* __restrict__ Q, const unsigned* __restrict__ K,
                   const unsigned* __restrict__ V, float* __restrict__ O)
{
    extern __shared__ unsigned sm[];
    unsigned* Qs = sm + SM_Q;
    unsigned* Ks = sm + SM_K;
    unsigned* Ps = sm + SM_P;
    unsigned* Vs = sm + SM_V;

    const int tid  = threadIdx.x;
    const int lane = tid & 31;
    const int w    = tid >> 5;
    const int qb   = blockIdx.x;
    const int h    = blockIdx.y;
    const int n    = blockIdx.z;

    const int qr   = (lane >> 2);    // 0..7
    const int qc   = (lane & 3);     // 0..3

    const unsigned* Qbase = Q + (size_t)(n * S_LEN + qb * 64) * E_DIM + h * HD;
    const unsigned* Kbase = K + (size_t)(n * T_LEN) * E_DIM + h * HD;
    const unsigned* Vbase = V + (size_t)(n * T_LEN) * E_DIM + h * HD;

    // Load Q tile (64x64) — already tf32 bits, pure copy
#pragma unroll
    for (int p = 0; p < 8; p++) {
        int f = tid + p * 128;        // 0..1023
        int r = f >> 4;               // 0..63
        int c = (f & 15) << 2;        // 0..60
        uint4 v = *(const uint4*)(Qbase + (size_t)r * E_DIM + c);
        Qs[r * QSTR + c + 0] = v.x;
        Qs[r * QSTR + c + 1] = v.y;
        Qs[r * QSTR + c + 2] = v.z;
        Qs[r * QSTR + c + 3] = v.w;
    }

    float oacc[8][4];
#pragma unroll
    for (int nt = 0; nt < 8; nt++)
#pragma unroll
        for (int c = 0; c < 4; c++) oacc[nt][c] = 0.f;
    float mr0 = -1e30f, mr1 = -1e30f, lr0 = 0.f, lr1 = 0.f;

    for (int t0 = 0; t0 < T_LEN; t0 += 64) {
        // Load K and V tiles — pure copies
#pragma unroll
        for (int p = 0; p < 8; p++) {
            int f = tid + p * 128;
            int r = f >> 4;
            int c = (f & 15) << 2;
            uint4 kv = *(const uint4*)(Kbase + (size_t)(t0 + r) * E_DIM + c);
            Ks[r * QSTR + c + 0] = kv.x;
            Ks[r * QSTR + c + 1] = kv.y;
            Ks[r * QSTR + c + 2] = kv.z;
            Ks[r * QSTR + c + 3] = kv.w;
            uint4 vv = *(const uint4*)(Vbase + (size_t)(t0 + r) * E_DIM + c);
            *(uint4*)(Vs + r * VSTR + c) = vv;
        }
        __syncthreads();

        // S = Q * K^T   (Q pre-scaled by 1/sqrt(HD) in the projection)
        float sacc[8][4];
#pragma unroll
        for (int nt = 0; nt < 8; nt++)
#pragma unroll
            for (int c = 0; c < 4; c++) sacc[nt][c] = 0.f;

#pragma unroll
        for (int kk = 0; kk < 8; kk++) {
            const int kb = kk * 8;
            unsigned a[4];
            int rbase = (w * 16 + qr) * QSTR + kb + qc;
            a[0] = Qs[rbase];
            a[1] = Qs[rbase + 8 * QSTR];
            a[2] = Qs[rbase + 4];
            a[3] = Qs[rbase + 8 * QSTR + 4];
#pragma unroll
            for (int nt = 0; nt < 8; nt++) {
                unsigned b[2];
                int bi = (nt * 8 + qr) * QSTR + kb + qc;
                b[0] = Ks[bi];
                b[1] = Ks[bi + 4];
                mma_tf32(sacc[nt], a, b);
            }
        }

        // Online softmax: thread owns rows r0 = w*16+qr (c0,c1) and r0+8 (c2,c3)
        float mx0 = -1e30f, mx1 = -1e30f;
#pragma unroll
        for (int nt = 0; nt < 8; nt++) {
            mx0 = fmaxf(mx0, fmaxf(sacc[nt][0], sacc[nt][1]));
            mx1 = fmaxf(mx1, fmaxf(sacc[nt][2], sacc[nt][3]));
        }
        mx0 = fmaxf(mx0, __shfl_xor_sync(0xffffffffu, mx0, 1));
        mx0 = fmaxf(mx0, __shfl_xor_sync(0xffffffffu, mx0, 2));
        mx1 = fmaxf(mx1, __shfl_xor_sync(0xffffffffu, mx1, 1));
        mx1 = fmaxf(mx1, __shfl_xor_sync(0xffffffffu, mx1, 2));

        float mn0 = fmaxf(mr0, mx0);
        float mn1 = fmaxf(mr1, mx1);
        float al0 = __expf(mr0 - mn0);
        float al1 = __expf(mr1 - mn1);
        mr0 = mn0;
        mr1 = mn1;

        float ls0 = 0.f, ls1 = 0.f;
        int prow0 = (w * 16 + qr) * QSTR + 2 * qc;
        int prow1 = prow0 + 8 * QSTR;
#pragma unroll
        for (int nt = 0; nt < 8; nt++) {
            float p00 = __expf(sacc[nt][0] - mn0);
            float p01 = __expf(sacc[nt][1] - mn0);
            float p10 = __expf(sacc[nt][2] - mn1);
            float p11 = __expf(sacc[nt][3] - mn1);
            ls0 += p00 + p01;
            ls1 += p10 + p11;
            Ps[prow0 + nt * 8]     = f2tf32(p00);
            Ps[prow0 + nt * 8 + 1] = f2tf32(p01);
            Ps[prow1 + nt * 8]     = f2tf32(p10);
            Ps[prow1 + nt * 8 + 1] = f2tf32(p11);
            oacc[nt][0] *= al0;
            oacc[nt][1] *= al0;
            oacc[nt][2] *= al1;
            oacc[nt][3] *= al1;
        }
        ls0 += __shfl_xor_sync(0xffffffffu, ls0, 1);
        ls0 += __shfl_xor_sync(0xffffffffu, ls0, 2);
        ls1 += __shfl_xor_sync(0xffffffffu, ls1, 1);
        ls1 += __shfl_xor_sync(0xffffffffu, ls1, 2);
        lr0 = lr0 * al0 + ls0;
        lr1 = lr1 * al1 + ls1;

        __syncwarp();   // P rows of this warp visible warp-wide

        // O += P * V   (m=q16, k=t, n=d)
#pragma unroll
        for (int kk = 0; kk < 8; kk++) {
            const int kb = kk * 8;
            unsigned a[4];
            int rbase = (w * 16 + qr) * QSTR + kb + qc;
            a[0] = Ps[rbase];
            a[1] = Ps[rbase + 8 * QSTR];
            a[2] = Ps[rbase + 4];
            a[3] = Ps[rbase + 8 * QSTR + 4];
#pragma unroll
            for (int nt = 0; nt < 8; nt++) {
                unsigned b[2];
                int bi = (kb + qc) * VSTR + nt * 8 + qr;
                b[0] = Vs[bi];
                b[1] = Vs[bi + 4 * VSTR];
                mma_tf32(oacc[nt], a, b);
            }
        }
        __syncthreads();   // Ks/Vs consumed; safe to overwrite next iter
    }

    // Normalize and write out: O[n*S + qb*64 + row][h*64 + col]
    float inv0 = 1.f / lr0;
    float inv1 = 1.f / lr1;
    int grow0 = n * S_LEN + qb * 64 + w * 16 + qr;
    int gcol  = h * HD + 2 * qc;
#pragma unroll
    for (int nt = 0; nt < 8; nt++) {
        float2 o0, o1;
        o0.x = oacc[nt][0] * inv0;
        o0.y = oacc[nt][1] * inv0;
        o1.x = oacc[nt][2] * inv1;
        o1.y = oacc[nt][3] * inv1;
        *(float2*)(O + (size_t)grow0 * E_DIM + gcol + nt * 8)       = o0;
        *(float2*)(O + (size_t)(grow0 + 8) * E_DIM + gcol + nt * 8) = o1;
    }
}

// ---------------------------------------------------------------------------
// Launch
// ---------------------------------------------------------------------------
extern "C" void kernel_launch(void* const* d_in, const int* in_sizes, int n_in,
                              void* d_out, int out_size)
{
    const float* query = (const float*)d_in[0];
    const float* key   = (const float*)d_in[1];
    const float* value = (const float*)d_in[2];
    const float* Wq    = (const float*)d_in[3];
    const float* bq    = (const float*)d_in[4];
    const float* Wk    = (const float*)d_in[5];
    const float* bk    = (const float*)d_in[6];
    const float* Wv    = (const float*)d_in[7];
    const float* bv    = (const float*)d_in[8];
    const float* Wo    = (const float*)d_in[9];
    const float* bo    = (const float*)d_in[10];
    float* out = (float*)d_out;

    float *q_p, *k_p, *v_p, *ao_p;
    cudaGetSymbolAddress((void**)&q_p,  g_q);
    cudaGetSymbolAddress((void**)&k_p,  g_k);
    cudaGetSymbolAddress((void**)&v_p,  g_v);
    cudaGetSymbolAddress((void**)&ao_p, g_ao);

    // Fused QKV projections (z = 0,1,2)
    dim3 qkv_grid(E_DIM / 128, M_ROWS / 128, 3);   // 8 x 32 x 3
    gemm_qkv<<<qkv_grid, 256>>>(query, key, value,
                                Wq, bq, Wk, bk, Wv, bv,
                                q_p, k_p, v_p);

    // Flash attention: aim for 3 CTAs/SM
    int smem_bytes = SM_TOT * (int)sizeof(unsigned);   // 70656
    static int configured = 0;
    if (!configured) {
        cudaFuncSetAttribute(flash_attn_tc,
                             cudaFuncAttributeMaxDynamicSharedMemorySize, smem_bytes);
        cudaFuncSetAttribute(flash_attn_tc,
                             cudaFuncAttributePreferredSharedMemoryCarveout, 100);
        configured = 1;
    }
    dim3 attn_grid(S_LEN / 64, H_NUM, N_B);            // 32 x 16 x 2
    flash_attn_tc<<<attn_grid, 128, smem_bytes>>>(
        (const unsigned*)q_p, (const unsigned*)k_p, (const unsigned*)v_p, ao_p);

    // Output projection
    dim3 gemm_grid(E_DIM / 128, M_ROWS / 128);         // 8 x 32
    gemm_tc<<<gemm_grid, 256>>>(ao_p, Wo, bo, out, 1.0f, 0);
}

// round 9
// speedup vs baseline: 1.2864x; 1.0113x over previous
#include <cuda_runtime.h>
#include <math.h>

// Problem constants
#define N_B    2
#define S_LEN  2048
#define T_LEN  2048
#define E_DIM  1024
#define H_NUM  16
#define HD     64
#define M_ROWS (N_B * S_LEN)   // 4096

// Scratch (device globals -> no runtime allocation)
__device__ float g_q [M_ROWS * E_DIM];   // tf32 bit patterns
__device__ float g_k [M_ROWS * E_DIM];   // tf32 bit patterns
__device__ float g_v [M_ROWS * E_DIM];   // tf32 bit patterns
__device__ float g_ao[M_ROWS * E_DIM];   // fp32

// ---------------------------------------------------------------------------
// Helpers
// ---------------------------------------------------------------------------
__device__ __forceinline__ unsigned f2tf32(float f) {
    unsigned u;
    asm("cvt.rna.tf32.f32 %0, %1;" : "=r"(u) : "f"(f));
    return u;
}

__device__ __forceinline__ void mma_tf32(float* c, const unsigned* a, const unsigned* b) {
    asm volatile(
        "mma.sync.aligned.m16n8k8.row.col.f32.tf32.tf32.f32 "
        "{%0,%1,%2,%3}, {%4,%5,%6,%7}, {%8,%9}, {%0,%1,%2,%3};"
        : "+f"(c[0]), "+f"(c[1]), "+f"(c[2]), "+f"(c[3])
        : "r"(a[0]), "r"(a[1]), "r"(a[2]), "r"(a[3]), "r"(b[0]), "r"(b[1]));
}

__device__ __forceinline__ void cp16(void* dst_smem, const void* src_gmem) {
    unsigned d = (unsigned)__cvta_generic_to_shared(dst_smem);
    asm volatile("cp.async.ca.shared.global [%0], [%1], 16;" :: "r"(d), "l"(src_gmem));
}

// ---------------------------------------------------------------------------
// GEMM (tf32 tensor core, cp.async double-buffered):
// C[M,1024] = (A[M,1024] @ W[1024,1024] + bias) * scale
// 128x128 CTA tile, BK=32, 256 threads = 8 warps (2x4), warp tile 64x32.
// Smem holds RAW fp32; cvt.rna happens at fragment load (same math as before).
// ---------------------------------------------------------------------------
#define ASTR 36
#define BSTR 136
#define AS_WORDS (128 * ASTR)          // 4608
#define BS_WORDS (32 * BSTR)           // 4352
#define GEMM_SMEM_WORDS (2 * (AS_WORDS + BS_WORDS))   // 17920
#define GEMM_SMEM_BYTES (GEMM_SMEM_WORDS * 4)         // 71680

__device__ __forceinline__
void gemm_load_tile(const float* __restrict__ A, const float* __restrict__ W,
                    int m0, int n0, int kt, float* As, float* Bs, int tid)
{
#pragma unroll
    for (int p = 0; p < 4; p++) {
        int f = tid + p * 256;
        int r = f >> 3;
        int c = (f & 7) << 2;
        cp16(As + r * ASTR + c, A + (size_t)(m0 + r) * E_DIM + kt + c);
    }
#pragma unroll
    for (int p = 0; p < 4; p++) {
        int f = tid + p * 256;
        int r = f >> 5;
        int c = (f & 31) << 2;
        cp16(Bs + r * BSTR + c, W + (size_t)(kt + r) * E_DIM + n0 + c);
    }
    asm volatile("cp.async.commit_group;");
}

__device__ __forceinline__
void gemm_body(const float* __restrict__ A, const float* __restrict__ W,
               const float* __restrict__ bias, float* __restrict__ C,
               float scale, int tf32_out, int m0, int n0, float* sm)
{
    float* As[2] = { sm,                 sm + AS_WORDS };
    float* Bs[2] = { sm + 2 * AS_WORDS, sm + 2 * AS_WORDS + BS_WORDS };

    const int tid  = threadIdx.x;
    const int lane = tid & 31;
    const int w    = tid >> 5;
    const int wm   = (w >> 2) * 64;
    const int wn   = (w & 3) * 32;

    float acc[4][4][4];
#pragma unroll
    for (int mi = 0; mi < 4; mi++)
#pragma unroll
        for (int ni = 0; ni < 4; ni++)
#pragma unroll
            for (int c = 0; c < 4; c++) acc[mi][ni][c] = 0.f;

    gemm_load_tile(A, W, m0, n0, 0, As[0], Bs[0], tid);

    for (int it = 0; it < E_DIM / 32; it++) {
        if (it + 1 < E_DIM / 32) {
            gemm_load_tile(A, W, m0, n0, (it + 1) * 32,
                           As[(it + 1) & 1], Bs[(it + 1) & 1], tid);
            asm volatile("cp.async.wait_group 1;");
        } else {
            asm volatile("cp.async.wait_group 0;");
        }
        __syncthreads();

        const float* Ab = As[it & 1];
        const float* Bb = Bs[it & 1];
#pragma unroll
        for (int kk = 0; kk < 4; kk++) {
            const int kb = kk * 8;
            unsigned af[4][4];
#pragma unroll
            for (int mi = 0; mi < 4; mi++) {
                int rbase = wm + mi * 16 + (lane >> 2);
                int cbase = kb + (lane & 3);
                af[mi][0] = f2tf32(Ab[rbase * ASTR + cbase]);
                af[mi][1] = f2tf32(Ab[(rbase + 8) * ASTR + cbase]);
                af[mi][2] = f2tf32(Ab[rbase * ASTR + cbase + 4]);
                af[mi][3] = f2tf32(Ab[(rbase + 8) * ASTR + cbase + 4]);
            }
            unsigned bf[4][2];
#pragma unroll
            for (int ni = 0; ni < 4; ni++) {
                int kbase = kb + (lane & 3);
                int nbase = wn + ni * 8 + (lane >> 2);
                bf[ni][0] = f2tf32(Bb[kbase * BSTR + nbase]);
                bf[ni][1] = f2tf32(Bb[(kbase + 4) * BSTR + nbase]);
            }
#pragma unroll
            for (int mi = 0; mi < 4; mi++)
#pragma unroll
                for (int ni = 0; ni < 4; ni++)
                    mma_tf32(acc[mi][ni], af[mi], bf[ni]);
        }
        __syncthreads();
    }

#pragma unroll
    for (int mi = 0; mi < 4; mi++) {
#pragma unroll
        for (int ni = 0; ni < 4; ni++) {
            int row = m0 + wm + mi * 16 + (lane >> 2);
            int col = n0 + wn + ni * 8 + 2 * (lane & 3);
            float v00 = (acc[mi][ni][0] + bias[col])     * scale;
            float v01 = (acc[mi][ni][1] + bias[col + 1]) * scale;
            float v10 = (acc[mi][ni][2] + bias[col])     * scale;
            float v11 = (acc[mi][ni][3] + bias[col + 1]) * scale;
            float2 o0, o1;
            if (tf32_out) {
                o0.x = __uint_as_float(f2tf32(v00));
                o0.y = __uint_as_float(f2tf32(v01));
                o1.x = __uint_as_float(f2tf32(v10));
                o1.y = __uint_as_float(f2tf32(v11));
            } else {
                o0.x = v00; o0.y = v01; o1.x = v10; o1.y = v11;
            }
            *(float2*)(C + (size_t)row * E_DIM + col)       = o0;
            *(float2*)(C + (size_t)(row + 8) * E_DIM + col) = o1;
        }
    }
}

// Fused QKV projections: blockIdx.z selects operand set.
__global__ __launch_bounds__(256, 2)
void gemm_qkv(const float* __restrict__ query, const float* __restrict__ key,
              const float* __restrict__ value,
              const float* __restrict__ Wq, const float* __restrict__ bq,
              const float* __restrict__ Wk, const float* __restrict__ bk,
              const float* __restrict__ Wv, const float* __restrict__ bv,
              float* __restrict__ q_out, float* __restrict__ k_out,
              float* __restrict__ v_out)
{
    extern __shared__ float smf[];
    const int z = blockIdx.z;
    const float* A = (z == 0) ? query : (z == 1) ? key : value;
    const float* W = (z == 0) ? Wq    : (z == 1) ? Wk  : Wv;
    const float* b = (z == 0) ? bq    : (z == 1) ? bk  : bv;
    float*       C = (z == 0) ? q_out : (z == 1) ? k_out : v_out;
    float scale    = (z == 0) ? 0.125f : 1.0f;   // Q pre-scaled by 1/sqrt(HD)
    gemm_body(A, W, b, C, scale, 1, blockIdx.y * 128, blockIdx.x * 128, smf);
}

// Output projection (fp32 out).
__global__ __launch_bounds__(256, 2)
void gemm_tc(const float* __restrict__ A, const float* __restrict__ W,
             const float* __restrict__ bias, float* __restrict__ C,
             float scale, int tf32_out)
{
    extern __shared__ float smf[];
    gemm_body(A, W, bias, C, scale, tf32_out,
              blockIdx.y * 128, blockIdx.x * 128, smf);
}

// ---------------------------------------------------------------------------
// Flash attention v3, tf32 tensor core (pre-converted tf32 inputs).
// CTA = 128 threads (4 warps) per (n, h, 128-query block). T tiled by 64.
// Warp w owns q rows 32w..32w+31 (two m16 tiles). b-fragments are loaded once
// per (kk,nt) and reused across both m tiles -> fewer smem bytes per MAC.
// Smem:
//   Qs[128][68] [q][d]  Ks[64][68] [t][d]  Ps[128][68] [q][t]  Vs[64][72] [t][d]
// ---------------------------------------------------------------------------
#define QSTR 68
#define VSTR 72
#define SM_Q  0
#define SM_K  (128 * QSTR)
#define SM_P  (SM_K + 64 * QSTR)
#define SM_V  (SM_P + 128 * QSTR)
#define SM_WORDS (SM_V + 64 * VSTR)     // 26368 words
#define SM_BYTES (SM_WORDS * 4)         // 105472 B

__global__ __launch_bounds__(128, 2)
void flash_attn_tc(const unsigned* __restrict__ Q, const unsigned* __restrict__ K,
                   const unsigned* __restrict__ V, float* __restrict__ O)
{
    extern __shared__ unsigned sm[];
    unsigned* Qs = sm + SM_Q;
    unsigned* Ks = sm + SM_K;
    unsigned* Ps = sm + SM_P;
    unsigned* Vs = sm + SM_V;

    const int tid   = threadIdx.x;
    const int lane  = tid & 31;
    const int w     = tid >> 5;
    const int qr    = lane >> 2;    // 0..7
    const int qc    = lane & 3;     // 0..3
    const int wbase = w * 32;

    const int qb = blockIdx.x;      // 0..15
    const int h  = blockIdx.y;
    const int n  = blockIdx.z;

    const unsigned* Qbase = Q + (size_t)(n * S_LEN + qb * 128) * E_DIM + h * HD;
    const unsigned* Kbase = K + (size_t)(n * T_LEN) * E_DIM + h * HD;
    const unsigned* Vbase = V + (size_t)(n * T_LEN) * E_DIM + h * HD;

    // Load Q tile (128x64) — already tf32 bits, pure copy
#pragma unroll
    for (int p = 0; p < 16; p++) {
        int f = tid + p * 128;        // 0..2047
        int r = f >> 4;               // 0..127
        int c = (f & 15) << 2;        // 0..60
        uint4 v = *(const uint4*)(Qbase + (size_t)r * E_DIM + c);
        Qs[r * QSTR + c + 0] = v.x;
        Qs[r * QSTR + c + 1] = v.y;
        Qs[r * QSTR + c + 2] = v.z;
        Qs[r * QSTR + c + 3] = v.w;
    }

    float oacc[2][8][4];
#pragma unroll
    for (int mi = 0; mi < 2; mi++)
#pragma unroll
        for (int nt = 0; nt < 8; nt++)
#pragma unroll
            for (int c = 0; c < 4; c++) oacc[mi][nt][c] = 0.f;
    float mrv[2][2], lrv[2][2];
#pragma unroll
    for (int mi = 0; mi < 2; mi++)
#pragma unroll
        for (int hf = 0; hf < 2; hf++) { mrv[mi][hf] = -1e30f; lrv[mi][hf] = 0.f; }

    for (int t0 = 0; t0 < T_LEN; t0 += 64) {
        // Load K and V tiles — pure copies
#pragma unroll
        for (int p = 0; p < 8; p++) {
            int f = tid + p * 128;
            int r = f >> 4;
            int c = (f & 15) << 2;
            uint4 kv = *(const uint4*)(Kbase + (size_t)(t0 + r) * E_DIM + c);
            Ks[r * QSTR + c + 0] = kv.x;
            Ks[r * QSTR + c + 1] = kv.y;
            Ks[r * QSTR + c + 2] = kv.z;
            Ks[r * QSTR + c + 3] = kv.w;
            uint4 vv = *(const uint4*)(Vbase + (size_t)(t0 + r) * E_DIM + c);
            *(uint4*)(Vs + r * VSTR + c) = vv;
        }
        __syncthreads();

        // ---- S = Q K^T ----
        float sacc[2][8][4];
#pragma unroll
        for (int mi = 0; mi < 2; mi++)
#pragma unroll
            for (int nt = 0; nt < 8; nt++)
#pragma unroll
                for (int c = 0; c < 4; c++) sacc[mi][nt][c] = 0.f;

#pragma unroll
        for (int kk = 0; kk < 8; kk++) {
            const int kb = kk * 8;
            unsigned a0[4], a1[4];
            int r0 = (wbase + qr) * QSTR + kb + qc;
            a0[0] = Qs[r0];
            a0[1] = Qs[r0 + 8 * QSTR];
            a0[2] = Qs[r0 + 4];
            a0[3] = Qs[r0 + 8 * QSTR + 4];
            int r1 = r0 + 16 * QSTR;
            a1[0] = Qs[r1];
            a1[1] = Qs[r1 + 8 * QSTR];
            a1[2] = Qs[r1 + 4];
            a1[3] = Qs[r1 + 8 * QSTR + 4];
#pragma unroll
            for (int nt = 0; nt < 8; nt++) {
                unsigned b[2];
                int bi = (nt * 8 + qr) * QSTR + kb + qc;
                b[0] = Ks[bi];
                b[1] = Ks[bi + 4];
                mma_tf32(sacc[0][nt], a0, b);
                mma_tf32(sacc[1][nt], a1, b);
            }
        }

        // ---- online softmax ----
#pragma unroll
        for (int mi = 0; mi < 2; mi++) {
#pragma unroll
            for (int hf = 0; hf < 2; hf++) {
                float mx = -1e30f;
#pragma unroll
                for (int nt = 0; nt < 8; nt++)
                    mx = fmaxf(mx, fmaxf(sacc[mi][nt][2 * hf], sacc[mi][nt][2 * hf + 1]));
                mx = fmaxf(mx, __shfl_xor_sync(0xffffffffu, mx, 1));
                mx = fmaxf(mx, __shfl_xor_sync(0xffffffffu, mx, 2));
                float mn = fmaxf(mrv[mi][hf], mx);
                float al = __expf(mrv[mi][hf] - mn);
                mrv[mi][hf] = mn;
                float ls = 0.f;
                int prow = (wbase + mi * 16 + qr + 8 * hf) * QSTR + 2 * qc;
#pragma unroll
                for (int nt = 0; nt < 8; nt++) {
                    float p0 = __expf(sacc[mi][nt][2 * hf]     - mn);
                    float p1 = __expf(sacc[mi][nt][2 * hf + 1] - mn);
                    ls += p0 + p1;
                    Ps[prow + nt * 8]     = f2tf32(p0);
                    Ps[prow + nt * 8 + 1] = f2tf32(p1);
                    oacc[mi][nt][2 * hf]     *= al;
                    oacc[mi][nt][2 * hf + 1] *= al;
                }
                ls += __shfl_xor_sync(0xffffffffu, ls, 1);
                ls += __shfl_xor_sync(0xffffffffu, ls, 2);
                lrv[mi][hf] = lrv[mi][hf] * al + ls;
            }
        }
        __syncwarp();   // P rows of this warp visible warp-wide

        // ---- O += P V ----
#pragma unroll
        for (int kk = 0; kk < 8; kk++) {
            const int kb = kk * 8;
            unsigned a0[4], a1[4];
            int r0 = (wbase + qr) * QSTR + kb + qc;
            a0[0] = Ps[r0];
            a0[1] = Ps[r0 + 8 * QSTR];
            a0[2] = Ps[r0 + 4];
            a0[3] = Ps[r0 + 8 * QSTR + 4];
            int r1 = r0 + 16 * QSTR;
            a1[0] = Ps[r1];
            a1[1] = Ps[r1 + 8 * QSTR];
            a1[2] = Ps[r1 + 4];
            a1[3] = Ps[r1 + 8 * QSTR + 4];
#pragma unroll
            for (int nt = 0; nt < 8; nt++) {
                unsigned b[2];
                int bi = (kb + qc) * VSTR + nt * 8 + qr;
                b[0] = Vs[bi];
                b[1] = Vs[bi + 4 * VSTR];
                mma_tf32(oacc[0][nt], a0, b);
                mma_tf32(oacc[1][nt], a1, b);
            }
        }
        __syncthreads();   // Ks/Vs consumed; safe to overwrite next iter
    }

    // Normalize and write out: O[n*S + qb*128 + row][h*64 + col]
#pragma unroll
    for (int mi = 0; mi < 2; mi++) {
        float inv0 = 1.f / lrv[mi][0];
        float inv1 = 1.f / lrv[mi][1];
        int grow0 = n * S_LEN + qb * 128 + wbase + mi * 16 + qr;
        int gcol  = h * HD + 2 * qc;
#pragma unroll
        for (int nt = 0; nt < 8; nt++) {
            float2 o0, o1;
            o0.x = oacc[mi][nt][0] * inv0;
            o0.y = oacc[mi][nt][1] * inv0;
            o1.x = oacc[mi][nt][2] * inv1;
            o1.y = oacc[mi][nt][3] * inv1;
            *(float2*)(O + (size_t)grow0 * E_DIM + gcol + nt * 8)       = o0;
            *(float2*)(O + (size_t)(grow0 + 8) * E_DIM + gcol + nt * 8) = o1;
        }
    }
}

// ---------------------------------------------------------------------------
// Launch
// ---------------------------------------------------------------------------
extern "C" void kernel_launch(void* const* d_in, const int* in_sizes, int n_in,
                              void* d_out, int out_size)
{
    const float* query = (const float*)d_in[0];
    const float* key   = (const float*)d_in[1];
    const float* value = (const float*)d_in[2];
    const float* Wq    = (const float*)d_in[3];
    const float* bq    = (const float*)d_in[4];
    const float* Wk    = (const float*)d_in[5];
    const float* bk    = (const float*)d_in[6];
    const float* Wv    = (const float*)d_in[7];
    const float* bv    = (const float*)d_in[8];
    const float* Wo    = (const float*)d_in[9];
    const float* bo    = (const float*)d_in[10];
    float* out = (float*)d_out;

    float *q_p, *k_p, *v_p, *ao_p;
    cudaGetSymbolAddress((void**)&q_p,  g_q);
    cudaGetSymbolAddress((void**)&k_p,  g_k);
    cudaGetSymbolAddress((void**)&v_p,  g_v);
    cudaGetSymbolAddress((void**)&ao_p, g_ao);

    static int configured = 0;
    if (!configured) {
        cudaFuncSetAttribute(gemm_qkv,
                             cudaFuncAttributeMaxDynamicSharedMemorySize, GEMM_SMEM_BYTES);
        cudaFuncSetAttribute(gemm_tc,
                             cudaFuncAttributeMaxDynamicSharedMemorySize, GEMM_SMEM_BYTES);
        cudaFuncSetAttribute(flash_attn_tc,
                             cudaFuncAttributeMaxDynamicSharedMemorySize, SM_BYTES);
        cudaFuncSetAttribute(flash_attn_tc,
                             cudaFuncAttributePreferredSharedMemoryCarveout, 100);
        configured = 1;
    }

    // Fused QKV projections (z = 0,1,2)
    dim3 qkv_grid(E_DIM / 128, M_ROWS / 128, 3);   // 8 x 32 x 3
    gemm_qkv<<<qkv_grid, 256, GEMM_SMEM_BYTES>>>(query, key, value,
                                                 Wq, bq, Wk, bk, Wv, bv,
                                                 q_p, k_p, v_p);

    // Flash attention (q-tile 128)
    dim3 attn_grid(S_LEN / 128, H_NUM, N_B);       // 16 x 16 x 2
    flash_attn_tc<<<attn_grid, 128, SM_BYTES>>>(
        (const unsigned*)q_p, (const unsigned*)k_p, (const unsigned*)v_p, ao_p);

    // Output projection
    dim3 gemm_grid(E_DIM / 128, M_ROWS / 128);     // 8 x 32
    gemm_tc<<<gemm_grid, 256, GEMM_SMEM_BYTES>>>(ao_p, Wo, bo, out, 1.0f, 0);
}

// round 10
// speedup vs baseline: 1.3697x; 1.0647x over previous
#include <cuda_runtime.h>
#include <math.h>

// Problem constants
#define N_B    2
#define S_LEN  2048
#define T_LEN  2048
#define E_DIM  1024
#define H_NUM  16
#define HD     64
#define M_ROWS (N_B * S_LEN)   // 4096

// Scratch (device globals -> no runtime allocation)
__device__ float g_q [M_ROWS * E_DIM];   // tf32 bit patterns
__device__ float g_k [M_ROWS * E_DIM];   // tf32 bit patterns
__device__ float g_v [M_ROWS * E_DIM];   // tf32 bit patterns
__device__ float g_ao[M_ROWS * E_DIM];   // fp32

// ---------------------------------------------------------------------------
// Helpers
// ---------------------------------------------------------------------------
__device__ __forceinline__ unsigned f2tf32(float f) {
    unsigned u;
    asm("cvt.rna.tf32.f32 %0, %1;" : "=r"(u) : "f"(f));
    return u;
}

__device__ __forceinline__ void mma_tf32(float* c, const unsigned* a, const unsigned* b) {
    asm volatile(
        "mma.sync.aligned.m16n8k8.row.col.f32.tf32.tf32.f32 "
        "{%0,%1,%2,%3}, {%4,%5,%6,%7}, {%8,%9}, {%0,%1,%2,%3};"
        : "+f"(c[0]), "+f"(c[1]), "+f"(c[2]), "+f"(c[3])
        : "r"(a[0]), "r"(a[1]), "r"(a[2]), "r"(a[3]), "r"(b[0]), "r"(b[1]));
}

// ---------------------------------------------------------------------------
// GEMM (tf32 tensor core, R7 form): C = (A @ W + bias) * scale
// 128x128 CTA tile, BK=32, 256 threads = 8 warps (2x4), warp tile 64x32.
// cvt.rna at tile fill; tf32 bits in smem; single-buffered.
// ---------------------------------------------------------------------------
#define ASTR 36
#define BSTR 136

__device__ __forceinline__
void gemm_body(const float* __restrict__ A, const float* __restrict__ W,
               const float* __restrict__ bias, float* __restrict__ C,
               float scale, int tf32_out, int m0, int n0,
               unsigned* As, unsigned* Bs)
{
    const int tid  = threadIdx.x;
    const int lane = tid & 31;
    const int w    = tid >> 5;
    const int wm   = (w >> 2) * 64;
    const int wn   = (w & 3) * 32;

    float acc[4][4][4];
#pragma unroll
    for (int mi = 0; mi < 4; mi++)
#pragma unroll
        for (int ni = 0; ni < 4; ni++)
#pragma unroll
            for (int c = 0; c < 4; c++) acc[mi][ni][c] = 0.f;

    for (int kt = 0; kt < E_DIM; kt += 32) {
#pragma unroll
        for (int p = 0; p < 4; p++) {
            int f = tid + p * 256;
            int r = f >> 3;
            int c = (f & 7) << 2;
            float4 v = *(const float4*)(A + (size_t)(m0 + r) * E_DIM + kt + c);
            As[r * ASTR + c + 0] = f2tf32(v.x);
            As[r * ASTR + c + 1] = f2tf32(v.y);
            As[r * ASTR + c + 2] = f2tf32(v.z);
            As[r * ASTR + c + 3] = f2tf32(v.w);
        }
#pragma unroll
        for (int p = 0; p < 4; p++) {
            int f = tid + p * 256;
            int r = f >> 5;
            int c = (f & 31) << 2;
            float4 v = *(const float4*)(W + (size_t)(kt + r) * E_DIM + n0 + c);
            Bs[r * BSTR + c + 0] = f2tf32(v.x);
            Bs[r * BSTR + c + 1] = f2tf32(v.y);
            Bs[r * BSTR + c + 2] = f2tf32(v.z);
            Bs[r * BSTR + c + 3] = f2tf32(v.w);
        }
        __syncthreads();

#pragma unroll
        for (int kk = 0; kk < 4; kk++) {
            const int kb = kk * 8;
            unsigned af[4][4];
#pragma unroll
            for (int mi = 0; mi < 4; mi++) {
                int rbase = wm + mi * 16 + (lane >> 2);
                int cbase = kb + (lane & 3);
                af[mi][0] = As[rbase * ASTR + cbase];
                af[mi][1] = As[(rbase + 8) * ASTR + cbase];
                af[mi][2] = As[rbase * ASTR + cbase + 4];
                af[mi][3] = As[(rbase + 8) * ASTR + cbase + 4];
            }
            unsigned bf[4][2];
#pragma unroll
            for (int ni = 0; ni < 4; ni++) {
                int kbase = kb + (lane & 3);
                int nbase = wn + ni * 8 + (lane >> 2);
                bf[ni][0] = Bs[kbase * BSTR + nbase];
                bf[ni][1] = Bs[(kbase + 4) * BSTR + nbase];
            }
#pragma unroll
            for (int mi = 0; mi < 4; mi++)
#pragma unroll
                for (int ni = 0; ni < 4; ni++)
                    mma_tf32(acc[mi][ni], af[mi], bf[ni]);
        }
        __syncthreads();
    }

#pragma unroll
    for (int mi = 0; mi < 4; mi++) {
#pragma unroll
        for (int ni = 0; ni < 4; ni++) {
            int row = m0 + wm + mi * 16 + (lane >> 2);
            int col = n0 + wn + ni * 8 + 2 * (lane & 3);
            float v00 = (acc[mi][ni][0] + bias[col])     * scale;
            float v01 = (acc[mi][ni][1] + bias[col + 1]) * scale;
            float v10 = (acc[mi][ni][2] + bias[col])     * scale;
            float v11 = (acc[mi][ni][3] + bias[col + 1]) * scale;
            float2 o0, o1;
            if (tf32_out) {
                o0.x = __uint_as_float(f2tf32(v00));
                o0.y = __uint_as_float(f2tf32(v01));
                o1.x = __uint_as_float(f2tf32(v10));
                o1.y = __uint_as_float(f2tf32(v11));
            } else {
                o0.x = v00; o0.y = v01; o1.x = v10; o1.y = v11;
            }
            *(float2*)(C + (size_t)row * E_DIM + col)       = o0;
            *(float2*)(C + (size_t)(row + 8) * E_DIM + col) = o1;
        }
    }
}

// Fused QKV projections: blockIdx.z selects operand set.
__global__ __launch_bounds__(256, 2)
void gemm_qkv(const float* __restrict__ query, const float* __restrict__ key,
              const float* __restrict__ value,
              const float* __restrict__ Wq, const float* __restrict__ bq,
              const float* __restrict__ Wk, const float* __restrict__ bk,
              const float* __restrict__ Wv, const float* __restrict__ bv,
              float* __restrict__ q_out, float* __restrict__ k_out,
              float* __restrict__ v_out)
{
    __shared__ unsigned As[128 * ASTR];
    __shared__ unsigned Bs[32 * BSTR];
    const int z = blockIdx.z;
    const float* A = (z == 0) ? query : (z == 1) ? key : value;
    const float* W = (z == 0) ? Wq    : (z == 1) ? Wk  : Wv;
    const float* b = (z == 0) ? bq    : (z == 1) ? bk  : bv;
    float*       C = (z == 0) ? q_out : (z == 1) ? k_out : v_out;
    float scale    = (z == 0) ? 0.125f : 1.0f;   // Q pre-scaled by 1/sqrt(HD)
    gemm_body(A, W, b, C, scale, 1, blockIdx.y * 128, blockIdx.x * 128, As, Bs);
}

// Output projection (fp32 out).
__global__ __launch_bounds__(256, 2)
void gemm_tc(const float* __restrict__ A, const float* __restrict__ W,
             const float* __restrict__ bias, float* __restrict__ C,
             float scale, int tf32_out)
{
    __shared__ unsigned As[128 * ASTR];
    __shared__ unsigned Bs[32 * BSTR];
    gemm_body(A, W, bias, C, scale, tf32_out,
              blockIdx.y * 128, blockIdx.x * 128, As, Bs);
}

// ---------------------------------------------------------------------------
// Flash attention v3 (unchanged from R8 — measured improvement).
// CTA = 128 threads (4 warps) per (n, h, 128-query block). T tiled by 64.
// Warp w owns q rows 32w..32w+31 (two m16 tiles); b-fragments reused across
// both m tiles.
// Smem:
//   Qs[128][68] [q][d]  Ks[64][68] [t][d]  Ps[128][68] [q][t]  Vs[64][72] [t][d]
// ---------------------------------------------------------------------------
#define QSTR 68
#define VSTR 72
#define SM_Q  0
#define SM_K  (128 * QSTR)
#define SM_P  (SM_K + 64 * QSTR)
#define SM_V  (SM_P + 128 * QSTR)
#define SM_WORDS (SM_V + 64 * VSTR)     // 26368 words
#define SM_BYTES (SM_WORDS * 4)         // 105472 B

__global__ __launch_bounds__(128, 2)
void flash_attn_tc(const unsigned* __restrict__ Q, const unsigned* __restrict__ K,
                   const unsigned* __restrict__ V, float* __restrict__ O)
{
    extern __shared__ unsigned sm[];
    unsigned* Qs = sm + SM_Q;
    unsigned* Ks = sm + SM_K;
    unsigned* Ps = sm + SM_P;
    unsigned* Vs = sm + SM_V;

    const int tid   = threadIdx.x;
    const int lane  = tid & 31;
    const int w     = tid >> 5;
    const int qr    = lane >> 2;    // 0..7
    const int qc    = lane & 3;     // 0..3
    const int wbase = w * 32;

    const int qb = blockIdx.x;      // 0..15
    const int h  = blockIdx.y;
    const int n  = blockIdx.z;

    const unsigned* Qbase = Q + (size_t)(n * S_LEN + qb * 128) * E_DIM + h * HD;
    const unsigned* Kbase = K + (size_t)(n * T_LEN) * E_DIM + h * HD;
    const unsigned* Vbase = V + (size_t)(n * T_LEN) * E_DIM + h * HD;

    // Load Q tile (128x64) — already tf32 bits, pure copy
#pragma unroll
    for (int p = 0; p < 16; p++) {
        int f = tid + p * 128;        // 0..2047
        int r = f >> 4;               // 0..127
        int c = (f & 15) << 2;        // 0..60
        uint4 v = *(const uint4*)(Qbase + (size_t)r * E_DIM + c);
        Qs[r * QSTR + c + 0] = v.x;
        Qs[r * QSTR + c + 1] = v.y;
        Qs[r * QSTR + c + 2] = v.z;
        Qs[r * QSTR + c + 3] = v.w;
    }

    float oacc[2][8][4];
#pragma unroll
    for (int mi = 0; mi < 2; mi++)
#pragma unroll
        for (int nt = 0; nt < 8; nt++)
#pragma unroll
            for (int c = 0; c < 4; c++) oacc[mi][nt][c] = 0.f;
    float mrv[2][2], lrv[2][2];
#pragma unroll
    for (int mi = 0; mi < 2; mi++)
#pragma unroll
        for (int hf = 0; hf < 2; hf++) { mrv[mi][hf] = -1e30f; lrv[mi][hf] = 0.f; }

    for (int t0 = 0; t0 < T_LEN; t0 += 64) {
        // Load K and V tiles — pure copies
#pragma unroll
        for (int p = 0; p < 8; p++) {
            int f = tid + p * 128;
            int r = f >> 4;
            int c = (f & 15) << 2;
            uint4 kv = *(const uint4*)(Kbase + (size_t)(t0 + r) * E_DIM + c);
            Ks[r * QSTR + c + 0] = kv.x;
            Ks[r * QSTR + c + 1] = kv.y;
            Ks[r * QSTR + c + 2] = kv.z;
            Ks[r * QSTR + c + 3] = kv.w;
            uint4 vv = *(const uint4*)(Vbase + (size_t)(t0 + r) * E_DIM + c);
            *(uint4*)(Vs + r * VSTR + c) = vv;
        }
        __syncthreads();

        // ---- S = Q K^T ----
        float sacc[2][8][4];
#pragma unroll
        for (int mi = 0; mi < 2; mi++)
#pragma unroll
            for (int nt = 0; nt < 8; nt++)
#pragma unroll
                for (int c = 0; c < 4; c++) sacc[mi][nt][c] = 0.f;

#pragma unroll
        for (int kk = 0; kk < 8; kk++) {
            const int kb = kk * 8;
            unsigned a0[4], a1[4];
            int r0 = (wbase + qr) * QSTR + kb + qc;
            a0[0] = Qs[r0];
            a0[1] = Qs[r0 + 8 * QSTR];
            a0[2] = Qs[r0 + 4];
            a0[3] = Qs[r0 + 8 * QSTR + 4];
            int r1 = r0 + 16 * QSTR;
            a1[0] = Qs[r1];
            a1[1] = Qs[r1 + 8 * QSTR];
            a1[2] = Qs[r1 + 4];
            a1[3] = Qs[r1 + 8 * QSTR + 4];
#pragma unroll
            for (int nt = 0; nt < 8; nt++) {
                unsigned b[2];
                int bi = (nt * 8 + qr) * QSTR + kb + qc;
                b[0] = Ks[bi];
                b[1] = Ks[bi + 4];
                mma_tf32(sacc[0][nt], a0, b);
                mma_tf32(sacc[1][nt], a1, b);
            }
        }

        // ---- online softmax ----
#pragma unroll
        for (int mi = 0; mi < 2; mi++) {
#pragma unroll
            for (int hf = 0; hf < 2; hf++) {
                float mx = -1e30f;
#pragma unroll
                for (int nt = 0; nt < 8; nt++)
                    mx = fmaxf(mx, fmaxf(sacc[mi][nt][2 * hf], sacc[mi][nt][2 * hf + 1]));
                mx = fmaxf(mx, __shfl_xor_sync(0xffffffffu, mx, 1));
                mx = fmaxf(mx, __shfl_xor_sync(0xffffffffu, mx, 2));
                float mn = fmaxf(mrv[mi][hf], mx);
                float al = __expf(mrv[mi][hf] - mn);
                mrv[mi][hf] = mn;
                float ls = 0.f;
                int prow = (wbase + mi * 16 + qr + 8 * hf) * QSTR + 2 * qc;
#pragma unroll
                for (int nt = 0; nt < 8; nt++) {
                    float p0 = __expf(sacc[mi][nt][2 * hf]     - mn);
                    float p1 = __expf(sacc[mi][nt][2 * hf + 1] - mn);
                    ls += p0 + p1;
                    Ps[prow + nt * 8]     = f2tf32(p0);
                    Ps[prow + nt * 8 + 1] = f2tf32(p1);
                    oacc[mi][nt][2 * hf]     *= al;
                    oacc[mi][nt][2 * hf + 1] *= al;
                }
                ls += __shfl_xor_sync(0xffffffffu, ls, 1);
                ls += __shfl_xor_sync(0xffffffffu, ls, 2);
                lrv[mi][hf] = lrv[mi][hf] * al + ls;
            }
        }
        __syncwarp();   // P rows of this warp visible warp-wide

        // ---- O += P V ----
#pragma unroll
        for (int kk = 0; kk < 8; kk++) {
            const int kb = kk * 8;
            unsigned a0[4], a1[4];
            int r0 = (wbase + qr) * QSTR + kb + qc;
            a0[0] = Ps[r0];
            a0[1] = Ps[r0 + 8 * QSTR];
            a0[2] = Ps[r0 + 4];
            a0[3] = Ps[r0 + 8 * QSTR + 4];
            int r1 = r0 + 16 * QSTR;
            a1[0] = Ps[r1];
            a1[1] = Ps[r1 + 8 * QSTR];
            a1[2] = Ps[r1 + 4];
            a1[3] = Ps[r1 + 8 * QSTR + 4];
#pragma unroll
            for (int nt = 0; nt < 8; nt++) {
                unsigned b[2];
                int bi = (kb + qc) * VSTR + nt * 8 + qr;
                b[0] = Vs[bi];
                b[1] = Vs[bi + 4 * VSTR];
                mma_tf32(oacc[0][nt], a0, b);
                mma_tf32(oacc[1][nt], a1, b);
            }
        }
        __syncthreads();   // Ks/Vs consumed; safe to overwrite next iter
    }

    // Normalize and write out: O[n*S + qb*128 + row][h*64 + col]
#pragma unroll
    for (int mi = 0; mi < 2; mi++) {
        float inv0 = 1.f / lrv[mi][0];
        float inv1 = 1.f / lrv[mi][1];
        int grow0 = n * S_LEN + qb * 128 + wbase + mi * 16 + qr;
        int gcol  = h * HD + 2 * qc;
#pragma unroll
        for (int nt = 0; nt < 8; nt++) {
            float2 o0, o1;
            o0.x = oacc[mi][nt][0] * inv0;
            o0.y = oacc[mi][nt][1] * inv0;
            o1.x = oacc[mi][nt][2] * inv1;
            o1.y = oacc[mi][nt][3] * inv1;
            *(float2*)(O + (size_t)grow0 * E_DIM + gcol + nt * 8)       = o0;
            *(float2*)(O + (size_t)(grow0 + 8) * E_DIM + gcol + nt * 8) = o1;
        }
    }
}

// ---------------------------------------------------------------------------
// Launch
// ---------------------------------------------------------------------------
extern "C" void kernel_launch(void* const* d_in, const int* in_sizes, int n_in,
                              void* d_out, int out_size)
{
    const float* query = (const float*)d_in[0];
    const float* key   = (const float*)d_in[1];
    const float* value = (const float*)d_in[2];
    const float* Wq    = (const float*)d_in[3];
    const float* bq    = (const float*)d_in[4];
    const float* Wk    = (const float*)d_in[5];
    const float* bk    = (const float*)d_in[6];
    const float* Wv    = (const float*)d_in[7];
    const float* bv    = (const float*)d_in[8];
    const float* Wo    = (const float*)d_in[9];
    const float* bo    = (const float*)d_in[10];
    float* out = (float*)d_out;

    float *q_p, *k_p, *v_p, *ao_p;
    cudaGetSymbolAddress((void**)&q_p,  g_q);
    cudaGetSymbolAddress((void**)&k_p,  g_k);
    cudaGetSymbolAddress((void**)&v_p,  g_v);
    cudaGetSymbolAddress((void**)&ao_p, g_ao);

    static int configured = 0;
    if (!configured) {
        cudaFuncSetAttribute(flash_attn_tc,
                             cudaFuncAttributeMaxDynamicSharedMemorySize, SM_BYTES);
        cudaFuncSetAttribute(flash_attn_tc,
                             cudaFuncAttributePreferredSharedMemoryCarveout, 100);
        configured = 1;
    }

    // Fused QKV projections (z = 0,1,2)
    dim3 qkv_grid(E_DIM / 128, M_ROWS / 128, 3);   // 8 x 32 x 3
    gemm_qkv<<<qkv_grid, 256>>>(query, key, value,
                                Wq, bq, Wk, bk, Wv, bv,
                                q_p, k_p, v_p);

    // Flash attention (q-tile 128)
    dim3 attn_grid(S_LEN / 128, H_NUM, N_B);       // 16 x 16 x 2
    flash_attn_tc<<<attn_grid, 128, SM_BYTES>>>(
        (const unsigned*)q_p, (const unsigned*)k_p, (const unsigned*)v_p, ao_p);

    // Output projection
    dim3 gemm_grid(E_DIM / 128, M_ROWS / 128);     // 8 x 32
    gemm_tc<<<gemm_grid, 256>>>(ao_p, Wo, bo, out, 1.0f, 0);
}